// round 15
// baseline (speedup 1.0000x reference)
#include <cuda_runtime.h>
#include <cuda_fp16.h>
#include <cstdint>
#include <cstddef>

// Problem constants
#define BB   4
#define LQ   1024
#define LK   2048
#define NH   16
#define HD   64
#define QD   1024
#define KD   512
#define SCALE 0.125f   // 1/sqrt(64)

#define NSUB (LK / 64)           // 32 col-subtiles of 64 per attention row
#define TOTROWS (BB * NH * LQ)   // 65536 attention rows

// ---------------------------------------------------------------------------
// Scratch (device globals; allocation-free per harness rules).
// ---------------------------------------------------------------------------
__device__ __half g_inq [(size_t)BB * LQ * QD];      // 8 MB
__device__ __half g_ink [(size_t)BB * LK * KD];      // 8 MB
__device__ __half g_inv [(size_t)BB * LK * KD];      // 8 MB
__device__ __half g_wh  [(size_t)3 * 1024 * 1024];   // 6 MB  Wq|Wk|Wv|Wo
__device__ __half g_qh  [(size_t)BB * LQ * QD];      // 8 MB
__device__ __half g_kh  [(size_t)BB * LK * QD];      // 16 MB
__device__ __half g_vh  [(size_t)BB * LK * QD];      // 16 MB
__device__ __half g_ctxh[(size_t)BB * LQ * QD];      // 8 MB
__device__ __half g_ph  [(size_t)BB * NH * LQ * LK]; // 268 MB  p_tile (fp16)
__device__ float  g_pm  [(size_t)TOTROWS * NSUB];    // 8 MB
__device__ float  g_ps  [(size_t)TOTROWS * NSUB];    // 8 MB
__device__ float  g_fac [(size_t)TOTROWS * NSUB];    // 8 MB

// weight offsets in g_wh (halves)
#define WQ_OFF 0
#define WK_OFF (1024 * 1024)
#define WV_OFF (1024 * 1024 + 512 * 1024)
#define WO_OFF (2 * 1024 * 1024)

// ---------------------------------------------------------------------------
// Helpers
// ---------------------------------------------------------------------------
__device__ __forceinline__ void mma_f16(float c[4],
                                        const uint32_t a[4],
                                        const uint32_t b[2]) {
    asm volatile(
        "mma.sync.aligned.m16n8k16.row.col.f32.f16.f16.f32 "
        "{%0,%1,%2,%3}, {%4,%5,%6,%7}, {%8,%9}, {%0,%1,%2,%3};\n"
        : "+f"(c[0]), "+f"(c[1]), "+f"(c[2]), "+f"(c[3])
        : "r"(a[0]), "r"(a[1]), "r"(a[2]), "r"(a[3]),
          "r"(b[0]), "r"(b[1]));
}

__device__ __forceinline__ uint32_t smem_u32(const void* p) {
    uint32_t r;
    asm("{ .reg .u64 t; cvta.to.shared.u64 t, %1; cvt.u32.u64 %0, t; }"
        : "=r"(r) : "l"(p));
    return r;
}
__device__ __forceinline__ void cp16(void* dst_smem, const void* src_gmem) {
    asm volatile("cp.async.cg.shared.global [%0], [%1], 16;\n"
                 :: "r"(smem_u32(dst_smem)), "l"(src_gmem));
}
__device__ __forceinline__ void cp_commit() {
    asm volatile("cp.async.commit_group;\n");
}
template <int N>
__device__ __forceinline__ void cp_wait() {
    asm volatile("cp.async.wait_group %0;\n" :: "n"(N));
}

__device__ __forceinline__ uint32_t lds32h(const __half* p) {
    return *(const uint32_t*)p;
}
__device__ __forceinline__ uint32_t h2scale(uint32_t a, __half2 f) {
    __half2 r = __hmul2(*(__half2*)&a, f);
    return *(uint32_t*)&r;
}
// streaming 32-bit store (for p fp16x2)
__device__ __forceinline__ void stcs32(__half* p, __half2 v) {
    asm volatile("st.global.cs.b32 [%0], %1;\n" :: "l"(p), "r"(*(uint32_t*)&v));
}

// smem stride (halves): rows are 144 B (odd multiple of 16B -> conflict-free)
#define STRH64 72

// ---------------------------------------------------------------------------
// Merged fp32 -> fp16 conversion for all 7 buffers (compile-time boundaries)
// ---------------------------------------------------------------------------
#define C_N1 1048576u            // query float4s
#define C_N2 2097152u            // + key
#define C_N3 3145728u            // + value
#define C_N4 3407872u            // + Wq
#define C_N5 3538944u            // + Wk
#define C_N6 3670016u            // + Wv
#define C_NT 3932160u            // + Wo

__global__ void conv_all(const float4* __restrict__ q, const float4* __restrict__ k,
                         const float4* __restrict__ v, const float4* __restrict__ wq,
                         const float4* __restrict__ wk, const float4* __restrict__ wv,
                         const float4* __restrict__ wo,
                         __half2* dq, __half2* dk, __half2* dv, __half2* dwq,
                         __half2* dwk, __half2* dwv, __half2* dwo) {
    unsigned i = blockIdx.x * 256 + threadIdx.x;
    if (i >= C_NT) return;
    const float4* s; __half2* d; unsigned off;
    if (i < C_N3) {
        if (i < C_N1)      { s = q; d = dq; off = i; }
        else if (i < C_N2) { s = k; d = dk; off = i - C_N1; }
        else               { s = v; d = dv; off = i - C_N2; }
    } else {
        if (i < C_N4)      { s = wq; d = dwq; off = i - C_N3; }
        else if (i < C_N5) { s = wk; d = dwk; off = i - C_N4; }
        else if (i < C_N6) { s = wv; d = dwv; off = i - C_N5; }
        else               { s = wo; d = dwo; off = i - C_N6; }
    }
    float4 vv = s[off];
    d[2 * off]     = __floats2half2_rn(vv.x, vv.y);
    d[2 * off + 1] = __floats2half2_rn(vv.z, vv.w);
}

// ===========================================================================
// GEMM core (BK=64, block 128x128, 8 warps 4x2, warp tile 32x64). 2-stage.
// ===========================================================================
template <bool HALF_OUT>
__device__ __forceinline__
void gemm_body(const __half* __restrict__ A, const __half* __restrict__ W,
               const float* __restrict__ bias, void* __restrict__ Cv,
               int N, int K, int bm, int bn, __half* smh) {
    __half* As = smh;                      // [2][128][STRH64]
    __half* Bs = smh + 2 * 128 * STRH64;   // [2][128][STRH64]

    const int tid = threadIdx.x;
    const int w = tid >> 5, lane = tid & 31;
    const int g = lane >> 2, tig = lane & 3;
    const int wm = (w & 3) * 32, wn = (w >> 2) * 64;

    float acc[2][8][4] = {};
    const int S = K >> 6;

    auto prefetch = [&](int s, int buf) {
        const int k0 = s * 64;
        __half* Ab = As + buf * 128 * STRH64;
        __half* Bb = Bs + buf * 128 * STRH64;
        #pragma unroll
        for (int i = 0; i < 4; i++) {
            int ch = tid + i * 256;       // 0..1023
            int row = ch >> 3;            // 0..127
            int kc = (ch & 7) * 8;        // 0..56 halves
            cp16(Ab + row * STRH64 + kc, A + (size_t)(bm + row) * K + k0 + kc);
            cp16(Bb + row * STRH64 + kc, W + (size_t)(bn + row) * K + k0 + kc);
        }
    };

    prefetch(0, 0);
    cp_commit();

    for (int s = 0; s < S; s++) {
        const int buf = s & 1;
        if (s + 1 < S) { prefetch(s + 1, buf ^ 1); cp_commit(); cp_wait<1>(); }
        else           { cp_wait<0>(); }
        __syncthreads();

        const __half* Ab = As + buf * 128 * STRH64;
        const __half* Bb = Bs + buf * 128 * STRH64;
        #pragma unroll
        for (int kk = 0; kk < 64; kk += 16) {
            uint32_t af[2][4], bf[8][2];
            #pragma unroll
            for (int mf = 0; mf < 2; mf++) {
                int mb = wm + mf * 16;
                af[mf][0] = lds32h(Ab + (mb + g) * STRH64 + kk + 2 * tig);
                af[mf][1] = lds32h(Ab + (mb + g + 8) * STRH64 + kk + 2 * tig);
                af[mf][2] = lds32h(Ab + (mb + g) * STRH64 + kk + 2 * tig + 8);
                af[mf][3] = lds32h(Ab + (mb + g + 8) * STRH64 + kk + 2 * tig + 8);
            }
            #pragma unroll
            for (int nf = 0; nf < 8; nf++) {
                int nb = wn + nf * 8 + g;
                bf[nf][0] = lds32h(Bb + nb * STRH64 + kk + 2 * tig);
                bf[nf][1] = lds32h(Bb + nb * STRH64 + kk + 2 * tig + 8);
            }
            #pragma unroll
            for (int mf = 0; mf < 2; mf++)
                #pragma unroll
                for (int nf = 0; nf < 8; nf++)
                    mma_f16(acc[mf][nf], af[mf], bf[nf]);
        }
        __syncthreads();
    }

    #pragma unroll
    for (int mf = 0; mf < 2; mf++) {
        #pragma unroll
        for (int nf = 0; nf < 8; nf++) {
            int row = bm + wm + mf * 16 + g;
            int col = bn + wn + nf * 8 + tig * 2;
            float b0 = __ldg(bias + col);
            float b1 = __ldg(bias + col + 1);
            float c0 = acc[mf][nf][0] + b0, c1 = acc[mf][nf][1] + b1;
            float c2 = acc[mf][nf][2] + b0, c3 = acc[mf][nf][3] + b1;
            if (HALF_OUT) {
                __half* C = (__half*)Cv;
                *(__half2*)(C + (size_t)row * N + col) = __floats2half2_rn(c0, c1);
                *(__half2*)(C + (size_t)(row + 8) * N + col) = __floats2half2_rn(c2, c3);
            } else {
                float* C = (float*)Cv;
                *(float2*)(C + (size_t)row * N + col) = make_float2(c0, c1);
                *(float2*)(C + (size_t)(row + 8) * N + col) = make_float2(c2, c3);
            }
        }
    }
}

// ===========================================================================
// Merged Q/K/V projection: one launch, 1280 blocks.
// ===========================================================================
__global__ __launch_bounds__(256, 2)
void gemm_qkv(const __half* __restrict__ inq, const __half* __restrict__ ink,
              const __half* __restrict__ inv, const __half* __restrict__ wh,
              const float* __restrict__ bq, const float* __restrict__ bk,
              const float* __restrict__ bv,
              __half* __restrict__ qh, __half* __restrict__ kh,
              __half* __restrict__ vh) {
    extern __shared__ __half smh[];
    int blk = blockIdx.x;
    const __half *A, *W;
    const float* bias;
    __half* C;
    int K;
    if (blk < 256) {
        A = inq; W = wh + WQ_OFF; bias = bq; C = qh; K = QD;
    } else if (blk < 768) {
        blk -= 256;
        A = ink; W = wh + WK_OFF; bias = bk; C = kh; K = KD;
    } else {
        blk -= 768;
        A = inv; W = wh + WV_OFF; bias = bv; C = vh; K = KD;
    }
    const int bn = (blk & 7) * 128;
    const int bm = (blk >> 3) * 128;
    gemm_body<true>(A, W, bias, C, QD, K, bm, bn, smh);
}

// ===========================================================================
// O projection (fp32 out): grid (QD/128, BB*LQ/128)
// ===========================================================================
__global__ __launch_bounds__(256, 2)
void gemm_o(const __half* __restrict__ ctxh, const __half* __restrict__ wo,
            const float* __restrict__ bo, float* __restrict__ out) {
    extern __shared__ __half smh[];
    gemm_body<false>(ctxh, wo, bo, out, QD, QD,
                     blockIdx.y * 128, blockIdx.x * 128, smh);
}

// ===========================================================================
// Scores: p_tile = exp(SCALE*q.k - m_sub) fp16 (streaming stores) +
// per-(row, 64-col) stats. Grid: (LK/128, LQ/128, BB*NH)
// ===========================================================================
__global__ __launch_bounds__(256, 2)
void scores_h(const __half* __restrict__ qm, const __half* __restrict__ km,
              __half* __restrict__ ph, float* __restrict__ pm,
              float* __restrict__ ps) {
    extern __shared__ __half smh[];
    __half* As = smh;                      // [128][STRH64]
    __half* Bs = smh + 128 * STRH64;       // [128][STRH64]

    const int bh = blockIdx.z;
    const int b = bh >> 4, h = bh & 15;
    const __half* Aq = qm + (size_t)b * LQ * QD + h * HD;
    const __half* Ak = km + (size_t)b * LK * QD + h * HD;
    __half* Pp = ph + (size_t)bh * LQ * LK;

    const int tid = threadIdx.x;
    const int bm = blockIdx.y * 128;
    const int bn = blockIdx.x * 128;
    const int w = tid >> 5, lane = tid & 31;
    const int g = lane >> 2, tig = lane & 3;
    const int wm = (w & 3) * 32, wn = (w >> 2) * 64;
    const int sub = blockIdx.x * 2 + (w >> 2);

    #pragma unroll
    for (int i = 0; i < 4; i++) {
        int ch = tid + i * 256;
        int row = ch >> 3;
        int kc = (ch & 7) * 8;
        cp16(As + row * STRH64 + kc, Aq + (size_t)(bm + row) * QD + kc);
        cp16(Bs + row * STRH64 + kc, Ak + (size_t)(bn + row) * QD + kc);
    }
    cp_commit();
    cp_wait<0>();
    __syncthreads();

    float acc[2][8][4] = {};
    #pragma unroll
    for (int kk = 0; kk < 64; kk += 16) {
        uint32_t af[2][4], bf[8][2];
        #pragma unroll
        for (int mf = 0; mf < 2; mf++) {
            int mb = wm + mf * 16;
            af[mf][0] = lds32h(As + (mb + g) * STRH64 + kk + 2 * tig);
            af[mf][1] = lds32h(As + (mb + g + 8) * STRH64 + kk + 2 * tig);
            af[mf][2] = lds32h(As + (mb + g) * STRH64 + kk + 2 * tig + 8);
            af[mf][3] = lds32h(As + (mb + g + 8) * STRH64 + kk + 2 * tig + 8);
        }
        #pragma unroll
        for (int nf = 0; nf < 8; nf++) {
            int nb = wn + nf * 8 + g;
            bf[nf][0] = lds32h(Bs + nb * STRH64 + kk + 2 * tig);
            bf[nf][1] = lds32h(Bs + nb * STRH64 + kk + 2 * tig + 8);
        }
        #pragma unroll
        for (int mf = 0; mf < 2; mf++)
            #pragma unroll
            for (int nf = 0; nf < 8; nf++)
                mma_f16(acc[mf][nf], af[mf], bf[nf]);
    }

    #pragma unroll
    for (int mf = 0; mf < 2; mf++) {
        float mA = -1e30f, mB = -1e30f;
        #pragma unroll
        for (int nf = 0; nf < 8; nf++) {
            #pragma unroll
            for (int q = 0; q < 4; q++) acc[mf][nf][q] *= SCALE;
            mA = fmaxf(mA, fmaxf(acc[mf][nf][0], acc[mf][nf][1]));
            mB = fmaxf(mB, fmaxf(acc[mf][nf][2], acc[mf][nf][3]));
        }
        mA = fmaxf(mA, __shfl_xor_sync(0xFFFFFFFFu, mA, 1));
        mA = fmaxf(mA, __shfl_xor_sync(0xFFFFFFFFu, mA, 2));
        mB = fmaxf(mB, __shfl_xor_sync(0xFFFFFFFFu, mB, 1));
        mB = fmaxf(mB, __shfl_xor_sync(0xFFFFFFFFu, mB, 2));

        float sA = 0.f, sB = 0.f;
        #pragma unroll
        for (int nf = 0; nf < 8; nf++) {
            acc[mf][nf][0] = __expf(acc[mf][nf][0] - mA);
            acc[mf][nf][1] = __expf(acc[mf][nf][1] - mA);
            acc[mf][nf][2] = __expf(acc[mf][nf][2] - mB);
            acc[mf][nf][3] = __expf(acc[mf][nf][3] - mB);
            sA += acc[mf][nf][0] + acc[mf][nf][1];
            sB += acc[mf][nf][2] + acc[mf][nf][3];
        }
        sA += __shfl_xor_sync(0xFFFFFFFFu, sA, 1);
        sA += __shfl_xor_sync(0xFFFFFFFFu, sA, 2);
        sB += __shfl_xor_sync(0xFFFFFFFFu, sB, 1);
        sB += __shfl_xor_sync(0xFFFFFFFFu, sB, 2);

        int rowA = bm + wm + mf * 16 + g;
        #pragma unroll
        for (int nf = 0; nf < 8; nf++) {
            int col = bn + wn + nf * 8 + tig * 2;
            stcs32(Pp + (size_t)rowA * LK + col,
                   __floats2half2_rn(acc[mf][nf][0], acc[mf][nf][1]));
            stcs32(Pp + (size_t)(rowA + 8) * LK + col,
                   __floats2half2_rn(acc[mf][nf][2], acc[mf][nf][3]));
        }
        if (tig == 0) {
            size_t rA = (size_t)bh * LQ + rowA;
            pm[rA * NSUB + sub] = mA; ps[rA * NSUB + sub] = sA;
            pm[(rA + 8) * NSUB + sub] = mB; ps[(rA + 8) * NSUB + sub] = sB;
        }
    }
}

// ===========================================================================
// Per-row factors: ONE WARP PER ROW (lane t owns subtile t; NSUB == 32).
// ===========================================================================
__global__ __launch_bounds__(256)
void reduce_stats_k(const float* __restrict__ pm,
                    const float* __restrict__ ps,
                    float* __restrict__ fac) {
    const int row = blockIdx.x * 8 + (threadIdx.x >> 5);
    const int lane = threadIdx.x & 31;
    const size_t idx = (size_t)row * NSUB + lane;

    float m = pm[idx];
    float s = ps[idx];

    float mr = m;
    #pragma unroll
    for (int o = 16; o > 0; o >>= 1)
        mr = fmaxf(mr, __shfl_xor_sync(0xFFFFFFFFu, mr, o));

    float e = __expf(m - mr);
    float le = s * e;
    #pragma unroll
    for (int o = 16; o > 0; o >>= 1)
        le += __shfl_xor_sync(0xFFFFFFFFu, le, o);

    fac[idx] = e / le;
}

// ===========================================================================
// Context (BK=64, 2-stage, 3 CTAs/SM): attn fp32 = p*fac (streaming store);
// ctx = (p*fac) @ V. Grid: (LQ/128, BB*NH). Slab s == stat subtile s.
// acc is only 32 floats -> cap regs via launch_bounds(256,3) for occupancy.
// ===========================================================================
__global__ __launch_bounds__(256, 3)
void ctx_h(const __half* __restrict__ ph, const __half* __restrict__ vh,
           float* __restrict__ attn, __half* __restrict__ ctx,
           const float* __restrict__ fac) {
    extern __shared__ char smraw2[];
    __half* Ps = (__half*)smraw2;                              // [2][128][STRH64]
    __half* Vs = (__half*)(smraw2 + 2 * 128 * STRH64 * 2);     // [2][64][STRH64]
    float* facs = (float*)(smraw2 + 2 * 128 * STRH64 * 2 + 2 * 64 * STRH64 * 2);

    const int bh = blockIdx.y;
    const int b = bh >> 4, h = bh & 15;
    const __half* Pp = ph + (size_t)bh * LQ * LK;
    const __half* Vp = vh + (size_t)b * LK * QD + h * HD;
    float* Ap = attn + (size_t)bh * LQ * LK;

    const int tid = threadIdx.x;
    const int bm = blockIdx.x * 128;
    const int w = tid >> 5, lane = tid & 31;
    const int g = lane >> 2, tig = lane & 3;
    const int wm = (w & 3) * 32, wn = (w >> 2) * 32;

    {
        const float* fsrc = fac + ((size_t)bh * LQ + bm) * NSUB;
        #pragma unroll
        for (int i = 0; i < (128 * NSUB) / 256; i++)
            facs[i * 256 + tid] = fsrc[i * 256 + tid];
    }

    float acc[2][4][4] = {};

    auto prefetch = [&](int s, int buf) {
        const int k0 = s * 64;
        __half* Pb = Ps + buf * 128 * STRH64;
        __half* Vb = Vs + buf * 64 * STRH64;
        #pragma unroll
        for (int i = 0; i < 4; i++) {
            int ch = tid + i * 256;       // 0..1023
            int row = ch >> 3;            // 0..127
            int kc = (ch & 7) * 8;        // 0..56
            cp16(Pb + row * STRH64 + kc, Pp + (size_t)(bm + row) * LK + k0 + kc);
        }
        #pragma unroll
        for (int i = 0; i < 2; i++) {
            int ch = tid + i * 256;       // 0..511
            int kr = ch >> 3;             // 0..63
            int nc = (ch & 7) * 8;        // 0..56
            cp16(Vb + kr * STRH64 + nc, Vp + (size_t)(k0 + kr) * QD + nc);
        }
    };

    prefetch(0, 0);
    cp_commit();

    const int S = LK / 64;   // 32 slabs; slab s == subtile s
    for (int s = 0; s < S; s++) {
        const int buf = s & 1;
        if (s + 1 < S) { prefetch(s + 1, buf ^ 1); cp_commit(); cp_wait<1>(); }
        else           { cp_wait<0>(); }
        __syncthreads();

        const __half* Pb = Ps + buf * 128 * STRH64;
        const __half* Vb = Vs + buf * 64 * STRH64;
        const int k0 = s * 64;

        // attn write: p_fp32 = half(p) * factor (streaming store, no reuse)
        #pragma unroll
        for (int i = 0; i < 8; i++) {
            int ch = tid + i * 256;       // 0..2047
            int row = ch >> 4;            // 0..127
            int kc = (ch & 15) * 4;       // 0..60
            float f = facs[row * NSUB + s];
            __half2 h0 = *(const __half2*)(Pb + row * STRH64 + kc);
            __half2 h1 = *(const __half2*)(Pb + row * STRH64 + kc + 2);
            float4 o;
            o.x = __low2float(h0) * f;  o.y = __high2float(h0) * f;
            o.z = __low2float(h1) * f;  o.w = __high2float(h1) * f;
            __stcs((float4*)(Ap + (size_t)(bm + row) * LK + k0 + kc), o);
        }

        #pragma unroll
        for (int kk = 0; kk < 64; kk += 16) {
            uint32_t af[2][4], bf[4][2];
            #pragma unroll
            for (int mf = 0; mf < 2; mf++) {
                int mb = wm + mf * 16;
                __half2 fg = __float2half2_rn(facs[(mb + g) * NSUB + s]);
                __half2 f8 = __float2half2_rn(facs[(mb + g + 8) * NSUB + s]);
                af[mf][0] = h2scale(lds32h(Pb + (mb + g) * STRH64 + kk + 2 * tig), fg);
                af[mf][1] = h2scale(lds32h(Pb + (mb + g + 8) * STRH64 + kk + 2 * tig), f8);
                af[mf][2] = h2scale(lds32h(Pb + (mb + g) * STRH64 + kk + 2 * tig + 8), fg);
                af[mf][3] = h2scale(lds32h(Pb + (mb + g + 8) * STRH64 + kk + 2 * tig + 8), f8);
            }
            #pragma unroll
            for (int nf = 0; nf < 4; nf++) {
                int nb = wn + nf * 8 + g;
                __half2 b0 = __halves2half2(Vb[(kk + 2 * tig) * STRH64 + nb],
                                            Vb[(kk + 2 * tig + 1) * STRH64 + nb]);
                __half2 b1 = __halves2half2(Vb[(kk + 2 * tig + 8) * STRH64 + nb],
                                            Vb[(kk + 2 * tig + 9) * STRH64 + nb]);
                bf[nf][0] = *(uint32_t*)&b0;
                bf[nf][1] = *(uint32_t*)&b1;
            }
            #pragma unroll
            for (int mf = 0; mf < 2; mf++)
                #pragma unroll
                for (int nf = 0; nf < 4; nf++)
                    mma_f16(acc[mf][nf], af[mf], bf[nf]);
        }
        __syncthreads();
    }

    #pragma unroll
    for (int mf = 0; mf < 2; mf++) {
        #pragma unroll
        for (int nf = 0; nf < 4; nf++) {
            int row = bm + wm + mf * 16 + g;
            int col = h * HD + wn + nf * 8 + tig * 2;
            *(__half2*)(ctx + (size_t)(b * LQ + row) * QD + col) =
                __floats2half2_rn(acc[mf][nf][0], acc[mf][nf][1]);
            *(__half2*)(ctx + (size_t)(b * LQ + row + 8) * QD + col) =
                __floats2half2_rn(acc[mf][nf][2], acc[mf][nf][3]);
        }
    }
}

// ---------------------------------------------------------------------------
// kernel_launch
// ---------------------------------------------------------------------------
extern "C" void kernel_launch(void* const* d_in, const int* in_sizes, int n_in,
                              void* d_out, int out_size) {
    const float* query = (const float*)d_in[0];
    const float* key   = (const float*)d_in[1];
    const float* value = (const float*)d_in[2];
    const float* Wq = (const float*)d_in[3];
    const float* bq = (const float*)d_in[4];
    const float* Wk = (const float*)d_in[5];
    const float* bk = (const float*)d_in[6];
    const float* Wv = (const float*)d_in[7];
    const float* bv = (const float*)d_in[8];
    const float* Wo = (const float*)d_in[9];
    const float* bo = (const float*)d_in[10];

    float* out  = (float*)d_out;
    float* attn = out + (size_t)BB * LQ * QD;

    __half *inq, *ink, *inv, *wh, *qh, *kh, *vhp, *ctxh, *php;
    float *pm, *ps, *facp;
    cudaGetSymbolAddress((void**)&inq, g_inq);
    cudaGetSymbolAddress((void**)&ink, g_ink);
    cudaGetSymbolAddress((void**)&inv, g_inv);
    cudaGetSymbolAddress((void**)&wh,  g_wh);
    cudaGetSymbolAddress((void**)&qh,  g_qh);
    cudaGetSymbolAddress((void**)&kh,  g_kh);
    cudaGetSymbolAddress((void**)&vhp, g_vh);
    cudaGetSymbolAddress((void**)&ctxh, g_ctxh);
    cudaGetSymbolAddress((void**)&php, g_ph);
    cudaGetSymbolAddress((void**)&pm, g_pm);
    cudaGetSymbolAddress((void**)&ps, g_ps);
    cudaGetSymbolAddress((void**)&facp, g_fac);

    const int SMEM_GEMM = 2 * 2 * 128 * STRH64 * 2;                      // 73728 B
    const int SMEM_SC   = 2 * 128 * STRH64 * 2;                          // 36864 B
    const int SMEM_CTX  = 2 * 128 * STRH64 * 2 + 2 * 64 * STRH64 * 2
                        + 128 * NSUB * 4;                                // 71680 B
    cudaFuncSetAttribute(gemm_qkv, cudaFuncAttributeMaxDynamicSharedMemorySize, SMEM_GEMM);
    cudaFuncSetAttribute(gemm_o,   cudaFuncAttributeMaxDynamicSharedMemorySize, SMEM_GEMM);
    cudaFuncSetAttribute(scores_h, cudaFuncAttributeMaxDynamicSharedMemorySize, SMEM_SC);
    cudaFuncSetAttribute(ctx_h,    cudaFuncAttributeMaxDynamicSharedMemorySize, SMEM_CTX);

    // fp32 -> fp16 conversions (single merged launch)
    conv_all<<<C_NT / 256, 256>>>(
        (const float4*)query, (const float4*)key, (const float4*)value,
        (const float4*)Wq, (const float4*)Wk, (const float4*)Wv, (const float4*)Wo,
        (__half2*)inq, (__half2*)ink, (__half2*)inv,
        (__half2*)(wh + WQ_OFF), (__half2*)(wh + WK_OFF),
        (__half2*)(wh + WV_OFF), (__half2*)(wh + WO_OFF));

    // Q/K/V projections in ONE launch (1280 blocks)
    gemm_qkv<<<1280, 256, SMEM_GEMM>>>(inq, ink, inv, wh, bq, bk, bv, qh, kh, vhp);

    // Attention
    scores_h<<<dim3(LK / 128, LQ / 128, BB * NH), 256, SMEM_SC>>>(qh, kh, php, pm, ps);
    reduce_stats_k<<<TOTROWS / 8, 256>>>(pm, ps, facp);
    ctx_h<<<dim3(LQ / 128, BB * NH), 256, SMEM_CTX>>>(php, vhp, attn, ctxh, facp);

    // Output projection (fp32 out)
    gemm_o<<<dim3(QD / 128, (BB * LQ) / 128), 256, SMEM_GEMM>>>(ctxh, wh + WO_OFF, bo, out);
}

// round 16
// speedup vs baseline: 1.0088x; 1.0088x over previous
#include <cuda_runtime.h>
#include <cuda_fp16.h>
#include <cstdint>
#include <cstddef>

// Problem constants
#define BB   4
#define LQ   1024
#define LK   2048
#define NH   16
#define HD   64
#define QD   1024
#define KD   512
#define SCALE 0.125f   // 1/sqrt(64)

#define NSUB (LK / 64)           // 32 col-subtiles of 64 per attention row
#define TOTROWS (BB * NH * LQ)   // 65536 attention rows

// ---------------------------------------------------------------------------
// Scratch (device globals; allocation-free per harness rules).
// ---------------------------------------------------------------------------
__device__ __half g_inq [(size_t)BB * LQ * QD];      // 8 MB
__device__ __half g_ink [(size_t)BB * LK * KD];      // 8 MB
__device__ __half g_inv [(size_t)BB * LK * KD];      // 8 MB
__device__ __half g_wh  [(size_t)3 * 1024 * 1024];   // 6 MB  Wq|Wk|Wv|Wo
__device__ __half g_qh  [(size_t)BB * LQ * QD];      // 8 MB
__device__ __half g_kh  [(size_t)BB * LK * QD];      // 16 MB
__device__ __half g_vh  [(size_t)BB * LK * QD];      // 16 MB
__device__ __half g_ctxh[(size_t)BB * LQ * QD];      // 8 MB
__device__ __half g_ph  [(size_t)BB * NH * LQ * LK]; // 268 MB  p_tile (fp16)
__device__ float  g_pm  [(size_t)TOTROWS * NSUB];    // 8 MB
__device__ float  g_ps  [(size_t)TOTROWS * NSUB];    // 8 MB
__device__ float  g_fac [(size_t)TOTROWS * NSUB];    // 8 MB

// weight offsets in g_wh (halves)
#define WQ_OFF 0
#define WK_OFF (1024 * 1024)
#define WV_OFF (1024 * 1024 + 512 * 1024)
#define WO_OFF (2 * 1024 * 1024)

// ---------------------------------------------------------------------------
// Helpers
// ---------------------------------------------------------------------------
__device__ __forceinline__ void mma_f16(float c[4],
                                        const uint32_t a[4],
                                        const uint32_t b[2]) {
    asm volatile(
        "mma.sync.aligned.m16n8k16.row.col.f32.f16.f16.f32 "
        "{%0,%1,%2,%3}, {%4,%5,%6,%7}, {%8,%9}, {%0,%1,%2,%3};\n"
        : "+f"(c[0]), "+f"(c[1]), "+f"(c[2]), "+f"(c[3])
        : "r"(a[0]), "r"(a[1]), "r"(a[2]), "r"(a[3]),
          "r"(b[0]), "r"(b[1]));
}

__device__ __forceinline__ uint32_t smem_u32(const void* p) {
    uint32_t r;
    asm("{ .reg .u64 t; cvta.to.shared.u64 t, %1; cvt.u32.u64 %0, t; }"
        : "=r"(r) : "l"(p));
    return r;
}
__device__ __forceinline__ void cp16(void* dst_smem, const void* src_gmem) {
    asm volatile("cp.async.cg.shared.global [%0], [%1], 16;\n"
                 :: "r"(smem_u32(dst_smem)), "l"(src_gmem));
}
__device__ __forceinline__ void cp_commit() {
    asm volatile("cp.async.commit_group;\n");
}
template <int N>
__device__ __forceinline__ void cp_wait() {
    asm volatile("cp.async.wait_group %0;\n" :: "n"(N));
}

__device__ __forceinline__ uint32_t lds32h(const __half* p) {
    return *(const uint32_t*)p;
}
__device__ __forceinline__ uint32_t h2scale(uint32_t a, __half2 f) {
    __half2 r = __hmul2(*(__half2*)&a, f);
    return *(uint32_t*)&r;
}
// streaming 32-bit store (for p fp16x2)
__device__ __forceinline__ void stcs32(__half* p, __half2 v) {
    asm volatile("st.global.cs.b32 [%0], %1;\n" :: "l"(p), "r"(*(uint32_t*)&v));
}
// streaming float2 store (final fp32 output)
__device__ __forceinline__ void stcs64f(float* p, float2 v) {
    asm volatile("st.global.cs.v2.f32 [%0], {%1, %2};\n"
                 :: "l"(p), "f"(v.x), "f"(v.y));
}
// streaming read-once float4 load
__device__ __forceinline__ float4 ldcs128(const float4* p) {
    float4 v;
    asm volatile("ld.global.cs.nc.v4.f32 {%0, %1, %2, %3}, [%4];"
                 : "=f"(v.x), "=f"(v.y), "=f"(v.z), "=f"(v.w) : "l"(p));
    return v;
}

// smem stride (halves): rows are 144 B (odd multiple of 16B -> conflict-free)
#define STRH64 72

// ---------------------------------------------------------------------------
// Merged fp32 -> fp16 conversion for all 7 buffers (compile-time boundaries)
// ---------------------------------------------------------------------------
#define C_N1 1048576u            // query float4s
#define C_N2 2097152u            // + key
#define C_N3 3145728u            // + value
#define C_N4 3407872u            // + Wq
#define C_N5 3538944u            // + Wk
#define C_N6 3670016u            // + Wv
#define C_NT 3932160u            // + Wo

__global__ void conv_all(const float4* __restrict__ q, const float4* __restrict__ k,
                         const float4* __restrict__ v, const float4* __restrict__ wq,
                         const float4* __restrict__ wk, const float4* __restrict__ wv,
                         const float4* __restrict__ wo,
                         __half2* dq, __half2* dk, __half2* dv, __half2* dwq,
                         __half2* dwk, __half2* dwv, __half2* dwo) {
    unsigned i = blockIdx.x * 256 + threadIdx.x;
    if (i >= C_NT) return;
    const float4* s; __half2* d; unsigned off;
    if (i < C_N3) {
        if (i < C_N1)      { s = q; d = dq; off = i; }
        else if (i < C_N2) { s = k; d = dk; off = i - C_N1; }
        else               { s = v; d = dv; off = i - C_N2; }
    } else {
        if (i < C_N4)      { s = wq; d = dwq; off = i - C_N3; }
        else if (i < C_N5) { s = wk; d = dwk; off = i - C_N4; }
        else if (i < C_N6) { s = wv; d = dwv; off = i - C_N5; }
        else               { s = wo; d = dwo; off = i - C_N6; }
    }
    float4 vv = ldcs128(s + off);   // read-once: don't pollute L2
    d[2 * off]     = __floats2half2_rn(vv.x, vv.y);
    d[2 * off + 1] = __floats2half2_rn(vv.z, vv.w);
}

// ===========================================================================
// GEMM core (BK=64, block 128x128, 8 warps 4x2, warp tile 32x64). 2-stage.
// ===========================================================================
template <bool HALF_OUT>
__device__ __forceinline__
void gemm_body(const __half* __restrict__ A, const __half* __restrict__ W,
               const float* __restrict__ bias, void* __restrict__ Cv,
               int N, int K, int bm, int bn, __half* smh) {
    __half* As = smh;                      // [2][128][STRH64]
    __half* Bs = smh + 2 * 128 * STRH64;   // [2][128][STRH64]

    const int tid = threadIdx.x;
    const int w = tid >> 5, lane = tid & 31;
    const int g = lane >> 2, tig = lane & 3;
    const int wm = (w & 3) * 32, wn = (w >> 2) * 64;

    float acc[2][8][4] = {};
    const int S = K >> 6;

    auto prefetch = [&](int s, int buf) {
        const int k0 = s * 64;
        __half* Ab = As + buf * 128 * STRH64;
        __half* Bb = Bs + buf * 128 * STRH64;
        #pragma unroll
        for (int i = 0; i < 4; i++) {
            int ch = tid + i * 256;       // 0..1023
            int row = ch >> 3;            // 0..127
            int kc = (ch & 7) * 8;        // 0..56 halves
            cp16(Ab + row * STRH64 + kc, A + (size_t)(bm + row) * K + k0 + kc);
            cp16(Bb + row * STRH64 + kc, W + (size_t)(bn + row) * K + k0 + kc);
        }
    };

    prefetch(0, 0);
    cp_commit();

    for (int s = 0; s < S; s++) {
        const int buf = s & 1;
        if (s + 1 < S) { prefetch(s + 1, buf ^ 1); cp_commit(); cp_wait<1>(); }
        else           { cp_wait<0>(); }
        __syncthreads();

        const __half* Ab = As + buf * 128 * STRH64;
        const __half* Bb = Bs + buf * 128 * STRH64;
        #pragma unroll
        for (int kk = 0; kk < 64; kk += 16) {
            uint32_t af[2][4], bf[8][2];
            #pragma unroll
            for (int mf = 0; mf < 2; mf++) {
                int mb = wm + mf * 16;
                af[mf][0] = lds32h(Ab + (mb + g) * STRH64 + kk + 2 * tig);
                af[mf][1] = lds32h(Ab + (mb + g + 8) * STRH64 + kk + 2 * tig);
                af[mf][2] = lds32h(Ab + (mb + g) * STRH64 + kk + 2 * tig + 8);
                af[mf][3] = lds32h(Ab + (mb + g + 8) * STRH64 + kk + 2 * tig + 8);
            }
            #pragma unroll
            for (int nf = 0; nf < 8; nf++) {
                int nb = wn + nf * 8 + g;
                bf[nf][0] = lds32h(Bb + nb * STRH64 + kk + 2 * tig);
                bf[nf][1] = lds32h(Bb + nb * STRH64 + kk + 2 * tig + 8);
            }
            #pragma unroll
            for (int mf = 0; mf < 2; mf++)
                #pragma unroll
                for (int nf = 0; nf < 8; nf++)
                    mma_f16(acc[mf][nf], af[mf], bf[nf]);
        }
        __syncthreads();
    }

    #pragma unroll
    for (int mf = 0; mf < 2; mf++) {
        #pragma unroll
        for (int nf = 0; nf < 8; nf++) {
            int row = bm + wm + mf * 16 + g;
            int col = bn + wn + nf * 8 + tig * 2;
            float b0 = __ldg(bias + col);
            float b1 = __ldg(bias + col + 1);
            float c0 = acc[mf][nf][0] + b0, c1 = acc[mf][nf][1] + b1;
            float c2 = acc[mf][nf][2] + b0, c3 = acc[mf][nf][3] + b1;
            if (HALF_OUT) {
                __half* C = (__half*)Cv;
                *(__half2*)(C + (size_t)row * N + col) = __floats2half2_rn(c0, c1);
                *(__half2*)(C + (size_t)(row + 8) * N + col) = __floats2half2_rn(c2, c3);
            } else {
                // final fp32 output: streaming stores (never re-read on device)
                float* C = (float*)Cv;
                stcs64f(C + (size_t)row * N + col, make_float2(c0, c1));
                stcs64f(C + (size_t)(row + 8) * N + col, make_float2(c2, c3));
            }
        }
    }
}

// ===========================================================================
// Merged Q/K/V projection: one launch, 1280 blocks.
// ===========================================================================
__global__ __launch_bounds__(256, 2)
void gemm_qkv(const __half* __restrict__ inq, const __half* __restrict__ ink,
              const __half* __restrict__ inv, const __half* __restrict__ wh,
              const float* __restrict__ bq, const float* __restrict__ bk,
              const float* __restrict__ bv,
              __half* __restrict__ qh, __half* __restrict__ kh,
              __half* __restrict__ vh) {
    extern __shared__ __half smh[];
    int blk = blockIdx.x;
    const __half *A, *W;
    const float* bias;
    __half* C;
    int K;
    if (blk < 256) {
        A = inq; W = wh + WQ_OFF; bias = bq; C = qh; K = QD;
    } else if (blk < 768) {
        blk -= 256;
        A = ink; W = wh + WK_OFF; bias = bk; C = kh; K = KD;
    } else {
        blk -= 768;
        A = inv; W = wh + WV_OFF; bias = bv; C = vh; K = KD;
    }
    const int bn = (blk & 7) * 128;
    const int bm = (blk >> 3) * 128;
    gemm_body<true>(A, W, bias, C, QD, K, bm, bn, smh);
}

// ===========================================================================
// O projection (fp32 out, streaming): grid (QD/128, BB*LQ/128)
// ===========================================================================
__global__ __launch_bounds__(256, 2)
void gemm_o(const __half* __restrict__ ctxh, const __half* __restrict__ wo,
            const float* __restrict__ bo, float* __restrict__ out) {
    extern __shared__ __half smh[];
    gemm_body<false>(ctxh, wo, bo, out, QD, QD,
                     blockIdx.y * 128, blockIdx.x * 128, smh);
}

// ===========================================================================
// Scores: p_tile = exp(SCALE*q.k - m_sub) fp16 (streaming stores) +
// per-(row, 64-col) stats. Grid: (LK/128, LQ/128, BB*NH)
// ===========================================================================
__global__ __launch_bounds__(256, 2)
void scores_h(const __half* __restrict__ qm, const __half* __restrict__ km,
              __half* __restrict__ ph, float* __restrict__ pm,
              float* __restrict__ ps) {
    extern __shared__ __half smh[];
    __half* As = smh;                      // [128][STRH64]
    __half* Bs = smh + 128 * STRH64;       // [128][STRH64]

    const int bh = blockIdx.z;
    const int b = bh >> 4, h = bh & 15;
    const __half* Aq = qm + (size_t)b * LQ * QD + h * HD;
    const __half* Ak = km + (size_t)b * LK * QD + h * HD;
    __half* Pp = ph + (size_t)bh * LQ * LK;

    const int tid = threadIdx.x;
    const int bm = blockIdx.y * 128;
    const int bn = blockIdx.x * 128;
    const int w = tid >> 5, lane = tid & 31;
    const int g = lane >> 2, tig = lane & 3;
    const int wm = (w & 3) * 32, wn = (w >> 2) * 64;
    const int sub = blockIdx.x * 2 + (w >> 2);

    #pragma unroll
    for (int i = 0; i < 4; i++) {
        int ch = tid + i * 256;
        int row = ch >> 3;
        int kc = (ch & 7) * 8;
        cp16(As + row * STRH64 + kc, Aq + (size_t)(bm + row) * QD + kc);
        cp16(Bs + row * STRH64 + kc, Ak + (size_t)(bn + row) * QD + kc);
    }
    cp_commit();
    cp_wait<0>();
    __syncthreads();

    float acc[2][8][4] = {};
    #pragma unroll
    for (int kk = 0; kk < 64; kk += 16) {
        uint32_t af[2][4], bf[8][2];
        #pragma unroll
        for (int mf = 0; mf < 2; mf++) {
            int mb = wm + mf * 16;
            af[mf][0] = lds32h(As + (mb + g) * STRH64 + kk + 2 * tig);
            af[mf][1] = lds32h(As + (mb + g + 8) * STRH64 + kk + 2 * tig);
            af[mf][2] = lds32h(As + (mb + g) * STRH64 + kk + 2 * tig + 8);
            af[mf][3] = lds32h(As + (mb + g + 8) * STRH64 + kk + 2 * tig + 8);
        }
        #pragma unroll
        for (int nf = 0; nf < 8; nf++) {
            int nb = wn + nf * 8 + g;
            bf[nf][0] = lds32h(Bs + nb * STRH64 + kk + 2 * tig);
            bf[nf][1] = lds32h(Bs + nb * STRH64 + kk + 2 * tig + 8);
        }
        #pragma unroll
        for (int mf = 0; mf < 2; mf++)
            #pragma unroll
            for (int nf = 0; nf < 8; nf++)
                mma_f16(acc[mf][nf], af[mf], bf[nf]);
    }

    #pragma unroll
    for (int mf = 0; mf < 2; mf++) {
        float mA = -1e30f, mB = -1e30f;
        #pragma unroll
        for (int nf = 0; nf < 8; nf++) {
            #pragma unroll
            for (int q = 0; q < 4; q++) acc[mf][nf][q] *= SCALE;
            mA = fmaxf(mA, fmaxf(acc[mf][nf][0], acc[mf][nf][1]));
            mB = fmaxf(mB, fmaxf(acc[mf][nf][2], acc[mf][nf][3]));
        }
        mA = fmaxf(mA, __shfl_xor_sync(0xFFFFFFFFu, mA, 1));
        mA = fmaxf(mA, __shfl_xor_sync(0xFFFFFFFFu, mA, 2));
        mB = fmaxf(mB, __shfl_xor_sync(0xFFFFFFFFu, mB, 1));
        mB = fmaxf(mB, __shfl_xor_sync(0xFFFFFFFFu, mB, 2));

        float sA = 0.f, sB = 0.f;
        #pragma unroll
        for (int nf = 0; nf < 8; nf++) {
            acc[mf][nf][0] = __expf(acc[mf][nf][0] - mA);
            acc[mf][nf][1] = __expf(acc[mf][nf][1] - mA);
            acc[mf][nf][2] = __expf(acc[mf][nf][2] - mB);
            acc[mf][nf][3] = __expf(acc[mf][nf][3] - mB);
            sA += acc[mf][nf][0] + acc[mf][nf][1];
            sB += acc[mf][nf][2] + acc[mf][nf][3];
        }
        sA += __shfl_xor_sync(0xFFFFFFFFu, sA, 1);
        sA += __shfl_xor_sync(0xFFFFFFFFu, sA, 2);
        sB += __shfl_xor_sync(0xFFFFFFFFu, sB, 1);
        sB += __shfl_xor_sync(0xFFFFFFFFu, sB, 2);

        int rowA = bm + wm + mf * 16 + g;
        #pragma unroll
        for (int nf = 0; nf < 8; nf++) {
            int col = bn + wn + nf * 8 + tig * 2;
            stcs32(Pp + (size_t)rowA * LK + col,
                   __floats2half2_rn(acc[mf][nf][0], acc[mf][nf][1]));
            stcs32(Pp + (size_t)(rowA + 8) * LK + col,
                   __floats2half2_rn(acc[mf][nf][2], acc[mf][nf][3]));
        }
        if (tig == 0) {
            size_t rA = (size_t)bh * LQ + rowA;
            pm[rA * NSUB + sub] = mA; ps[rA * NSUB + sub] = sA;
            pm[(rA + 8) * NSUB + sub] = mB; ps[(rA + 8) * NSUB + sub] = sB;
        }
    }
}

// ===========================================================================
// Per-row factors: ONE WARP PER ROW (lane t owns subtile t; NSUB == 32).
// ===========================================================================
__global__ __launch_bounds__(256)
void reduce_stats_k(const float* __restrict__ pm,
                    const float* __restrict__ ps,
                    float* __restrict__ fac) {
    const int row = blockIdx.x * 8 + (threadIdx.x >> 5);
    const int lane = threadIdx.x & 31;
    const size_t idx = (size_t)row * NSUB + lane;

    float m = pm[idx];
    float s = ps[idx];

    float mr = m;
    #pragma unroll
    for (int o = 16; o > 0; o >>= 1)
        mr = fmaxf(mr, __shfl_xor_sync(0xFFFFFFFFu, mr, o));

    float e = __expf(m - mr);
    float le = s * e;
    #pragma unroll
    for (int o = 16; o > 0; o >>= 1)
        le += __shfl_xor_sync(0xFFFFFFFFu, le, o);

    fac[idx] = e / le;
}

// ===========================================================================
// Context (BK=64, 2-stage): attn fp32 = p*fac (streaming store);
// ctx = (p*fac) @ V. Grid: (LQ/128, BB*NH). Slab s == stat subtile s.
// ===========================================================================
__global__ __launch_bounds__(256, 2)
void ctx_h(const __half* __restrict__ ph, const __half* __restrict__ vh,
           float* __restrict__ attn, __half* __restrict__ ctx,
           const float* __restrict__ fac) {
    extern __shared__ char smraw2[];
    __half* Ps = (__half*)smraw2;                              // [2][128][STRH64]
    __half* Vs = (__half*)(smraw2 + 2 * 128 * STRH64 * 2);     // [2][64][STRH64]
    float* facs = (float*)(smraw2 + 2 * 128 * STRH64 * 2 + 2 * 64 * STRH64 * 2);

    const int bh = blockIdx.y;
    const int b = bh >> 4, h = bh & 15;
    const __half* Pp = ph + (size_t)bh * LQ * LK;
    const __half* Vp = vh + (size_t)b * LK * QD + h * HD;
    float* Ap = attn + (size_t)bh * LQ * LK;

    const int tid = threadIdx.x;
    const int bm = blockIdx.x * 128;
    const int w = tid >> 5, lane = tid & 31;
    const int g = lane >> 2, tig = lane & 3;
    const int wm = (w & 3) * 32, wn = (w >> 2) * 32;

    {
        const float* fsrc = fac + ((size_t)bh * LQ + bm) * NSUB;
        #pragma unroll
        for (int i = 0; i < (128 * NSUB) / 256; i++)
            facs[i * 256 + tid] = fsrc[i * 256 + tid];
    }

    float acc[2][4][4] = {};

    auto prefetch = [&](int s, int buf) {
        const int k0 = s * 64;
        __half* Pb = Ps + buf * 128 * STRH64;
        __half* Vb = Vs + buf * 64 * STRH64;
        #pragma unroll
        for (int i = 0; i < 4; i++) {
            int ch = tid + i * 256;       // 0..1023
            int row = ch >> 3;            // 0..127
            int kc = (ch & 7) * 8;        // 0..56
            cp16(Pb + row * STRH64 + kc, Pp + (size_t)(bm + row) * LK + k0 + kc);
        }
        #pragma unroll
        for (int i = 0; i < 2; i++) {
            int ch = tid + i * 256;       // 0..511
            int kr = ch >> 3;             // 0..63
            int nc = (ch & 7) * 8;        // 0..56
            cp16(Vb + kr * STRH64 + nc, Vp + (size_t)(k0 + kr) * QD + nc);
        }
    };

    prefetch(0, 0);
    cp_commit();

    const int S = LK / 64;   // 32 slabs; slab s == subtile s
    for (int s = 0; s < S; s++) {
        const int buf = s & 1;
        if (s + 1 < S) { prefetch(s + 1, buf ^ 1); cp_commit(); cp_wait<1>(); }
        else           { cp_wait<0>(); }
        __syncthreads();

        const __half* Pb = Ps + buf * 128 * STRH64;
        const __half* Vb = Vs + buf * 64 * STRH64;
        const int k0 = s * 64;

        // attn write: p_fp32 = half(p) * factor (streaming store, no reuse)
        #pragma unroll
        for (int i = 0; i < 8; i++) {
            int ch = tid + i * 256;       // 0..2047
            int row = ch >> 4;            // 0..127
            int kc = (ch & 15) * 4;       // 0..60
            float f = facs[row * NSUB + s];
            __half2 h0 = *(const __half2*)(Pb + row * STRH64 + kc);
            __half2 h1 = *(const __half2*)(Pb + row * STRH64 + kc + 2);
            float4 o;
            o.x = __low2float(h0) * f;  o.y = __high2float(h0) * f;
            o.z = __low2float(h1) * f;  o.w = __high2float(h1) * f;
            __stcs((float4*)(Ap + (size_t)(bm + row) * LK + k0 + kc), o);
        }

        #pragma unroll
        for (int kk = 0; kk < 64; kk += 16) {
            uint32_t af[2][4], bf[4][2];
            #pragma unroll
            for (int mf = 0; mf < 2; mf++) {
                int mb = wm + mf * 16;
                __half2 fg = __float2half2_rn(facs[(mb + g) * NSUB + s]);
                __half2 f8 = __float2half2_rn(facs[(mb + g + 8) * NSUB + s]);
                af[mf][0] = h2scale(lds32h(Pb + (mb + g) * STRH64 + kk + 2 * tig), fg);
                af[mf][1] = h2scale(lds32h(Pb + (mb + g + 8) * STRH64 + kk + 2 * tig), f8);
                af[mf][2] = h2scale(lds32h(Pb + (mb + g) * STRH64 + kk + 2 * tig + 8), fg);
                af[mf][3] = h2scale(lds32h(Pb + (mb + g + 8) * STRH64 + kk + 2 * tig + 8), f8);
            }
            #pragma unroll
            for (int nf = 0; nf < 4; nf++) {
                int nb = wn + nf * 8 + g;
                __half2 b0 = __halves2half2(Vb[(kk + 2 * tig) * STRH64 + nb],
                                            Vb[(kk + 2 * tig + 1) * STRH64 + nb]);
                __half2 b1 = __halves2half2(Vb[(kk + 2 * tig + 8) * STRH64 + nb],
                                            Vb[(kk + 2 * tig + 9) * STRH64 + nb]);
                bf[nf][0] = *(uint32_t*)&b0;
                bf[nf][1] = *(uint32_t*)&b1;
            }
            #pragma unroll
            for (int mf = 0; mf < 2; mf++)
                #pragma unroll
                for (int nf = 0; nf < 4; nf++)
                    mma_f16(acc[mf][nf], af[mf], bf[nf]);
        }
        __syncthreads();
    }

    #pragma unroll
    for (int mf = 0; mf < 2; mf++) {
        #pragma unroll
        for (int nf = 0; nf < 4; nf++) {
            int row = bm + wm + mf * 16 + g;
            int col = h * HD + wn + nf * 8 + tig * 2;
            *(__half2*)(ctx + (size_t)(b * LQ + row) * QD + col) =
                __floats2half2_rn(acc[mf][nf][0], acc[mf][nf][1]);
            *(__half2*)(ctx + (size_t)(b * LQ + row + 8) * QD + col) =
                __floats2half2_rn(acc[mf][nf][2], acc[mf][nf][3]);
        }
    }
}

// ---------------------------------------------------------------------------
// kernel_launch
// ---------------------------------------------------------------------------
extern "C" void kernel_launch(void* const* d_in, const int* in_sizes, int n_in,
                              void* d_out, int out_size) {
    const float* query = (const float*)d_in[0];
    const float* key   = (const float*)d_in[1];
    const float* value = (const float*)d_in[2];
    const float* Wq = (const float*)d_in[3];
    const float* bq = (const float*)d_in[4];
    const float* Wk = (const float*)d_in[5];
    const float* bk = (const float*)d_in[6];
    const float* Wv = (const float*)d_in[7];
    const float* bv = (const float*)d_in[8];
    const float* Wo = (const float*)d_in[9];
    const float* bo = (const float*)d_in[10];

    float* out  = (float*)d_out;
    float* attn = out + (size_t)BB * LQ * QD;

    __half *inq, *ink, *inv, *wh, *qh, *kh, *vhp, *ctxh, *php;
    float *pm, *ps, *facp;
    cudaGetSymbolAddress((void**)&inq, g_inq);
    cudaGetSymbolAddress((void**)&ink, g_ink);
    cudaGetSymbolAddress((void**)&inv, g_inv);
    cudaGetSymbolAddress((void**)&wh,  g_wh);
    cudaGetSymbolAddress((void**)&qh,  g_qh);
    cudaGetSymbolAddress((void**)&kh,  g_kh);
    cudaGetSymbolAddress((void**)&vhp, g_vh);
    cudaGetSymbolAddress((void**)&ctxh, g_ctxh);
    cudaGetSymbolAddress((void**)&php, g_ph);
    cudaGetSymbolAddress((void**)&pm, g_pm);
    cudaGetSymbolAddress((void**)&ps, g_ps);
    cudaGetSymbolAddress((void**)&facp, g_fac);

    const int SMEM_GEMM = 2 * 2 * 128 * STRH64 * 2;                      // 73728 B
    const int SMEM_SC   = 2 * 128 * STRH64 * 2;                          // 36864 B
    const int SMEM_CTX  = 2 * 128 * STRH64 * 2 + 2 * 64 * STRH64 * 2
                        + 128 * NSUB * 4;                                // 71680 B
    cudaFuncSetAttribute(gemm_qkv, cudaFuncAttributeMaxDynamicSharedMemorySize, SMEM_GEMM);
    cudaFuncSetAttribute(gemm_o,   cudaFuncAttributeMaxDynamicSharedMemorySize, SMEM_GEMM);
    cudaFuncSetAttribute(scores_h, cudaFuncAttributeMaxDynamicSharedMemorySize, SMEM_SC);
    cudaFuncSetAttribute(ctx_h,    cudaFuncAttributeMaxDynamicSharedMemorySize, SMEM_CTX);

    // fp32 -> fp16 conversions (single merged launch, streaming reads)
    conv_all<<<C_NT / 256, 256>>>(
        (const float4*)query, (const float4*)key, (const float4*)value,
        (const float4*)Wq, (const float4*)Wk, (const float4*)Wv, (const float4*)Wo,
        (__half2*)inq, (__half2*)ink, (__half2*)inv,
        (__half2*)(wh + WQ_OFF), (__half2*)(wh + WK_OFF),
        (__half2*)(wh + WV_OFF), (__half2*)(wh + WO_OFF));

    // Q/K/V projections in ONE launch (1280 blocks)
    gemm_qkv<<<1280, 256, SMEM_GEMM>>>(inq, ink, inv, wh, bq, bk, bv, qh, kh, vhp);

    // Attention
    scores_h<<<dim3(LK / 128, LQ / 128, BB * NH), 256, SMEM_SC>>>(qh, kh, php, pm, ps);
    reduce_stats_k<<<TOTROWS / 8, 256>>>(pm, ps, facp);
    ctx_h<<<dim3(LQ / 128, BB * NH), 256, SMEM_CTX>>>(php, vhp, attn, ctxh, facp);

    // Output projection (fp32 out, streaming stores)
    gemm_o<<<dim3(QD / 128, (BB * LQ) / 128), 256, SMEM_GEMM>>>(ctxh, wh + WO_OFF, bo, out);
}

// round 17
// speedup vs baseline: 1.0096x; 1.0008x over previous
#include <cuda_runtime.h>
#include <cuda_fp16.h>
#include <cstdint>
#include <cstddef>

// Problem constants
#define BB   4
#define LQ   1024
#define LK   2048
#define NH   16
#define HD   64
#define QD   1024
#define KD   512
#define SCALE 0.125f   // 1/sqrt(64)

#define NSUB (LK / 64)           // 32 col-subtiles of 64 per attention row
#define TOTROWS (BB * NH * LQ)   // 65536 attention rows

// ---------------------------------------------------------------------------
// Scratch (device globals; allocation-free per harness rules).
// ---------------------------------------------------------------------------
__device__ __half g_inq [(size_t)BB * LQ * QD];      // 8 MB
__device__ __half g_ink [(size_t)BB * LK * KD];      // 8 MB
__device__ __half g_inv [(size_t)BB * LK * KD];      // 8 MB
__device__ __half g_wh  [(size_t)3 * 1024 * 1024];   // 6 MB  Wq|Wk|Wv|Wo
__device__ __half g_qh  [(size_t)BB * LQ * QD];      // 8 MB
__device__ __half g_kh  [(size_t)BB * LK * QD];      // 16 MB
__device__ __half g_vh  [(size_t)BB * LK * QD];      // 16 MB
__device__ __half g_ctxh[(size_t)BB * LQ * QD];      // 8 MB
__device__ __half g_ph  [(size_t)BB * NH * LQ * LK]; // 268 MB  p_tile (fp16)
__device__ float  g_pm  [(size_t)TOTROWS * NSUB];    // 8 MB
__device__ float  g_ps  [(size_t)TOTROWS * NSUB];    // 8 MB
__device__ float  g_fac [(size_t)TOTROWS * NSUB];    // 8 MB

// weight offsets in g_wh (halves)
#define WQ_OFF 0
#define WK_OFF (1024 * 1024)
#define WV_OFF (1024 * 1024 + 512 * 1024)
#define WO_OFF (2 * 1024 * 1024)

// ---------------------------------------------------------------------------
// Helpers
// ---------------------------------------------------------------------------
__device__ __forceinline__ void mma_f16(float c[4],
                                        const uint32_t a[4],
                                        const uint32_t b[2]) {
    asm volatile(
        "mma.sync.aligned.m16n8k16.row.col.f32.f16.f16.f32 "
        "{%0,%1,%2,%3}, {%4,%5,%6,%7}, {%8,%9}, {%0,%1,%2,%3};\n"
        : "+f"(c[0]), "+f"(c[1]), "+f"(c[2]), "+f"(c[3])
        : "r"(a[0]), "r"(a[1]), "r"(a[2]), "r"(a[3]),
          "r"(b[0]), "r"(b[1]));
}

__device__ __forceinline__ uint32_t smem_u32(const void* p) {
    uint32_t r;
    asm("{ .reg .u64 t; cvta.to.shared.u64 t, %1; cvt.u32.u64 %0, t; }"
        : "=r"(r) : "l"(p));
    return r;
}
__device__ __forceinline__ void cp16(void* dst_smem, const void* src_gmem) {
    asm volatile("cp.async.cg.shared.global [%0], [%1], 16;\n"
                 :: "r"(smem_u32(dst_smem)), "l"(src_gmem));
}
__device__ __forceinline__ void cp_commit() {
    asm volatile("cp.async.commit_group;\n");
}
template <int N>
__device__ __forceinline__ void cp_wait() {
    asm volatile("cp.async.wait_group %0;\n" :: "n"(N));
}

__device__ __forceinline__ uint32_t lds32h(const __half* p) {
    return *(const uint32_t*)p;
}
__device__ __forceinline__ uint32_t h2scale(uint32_t a, __half2 f) {
    __half2 r = __hmul2(*(__half2*)&a, f);
    return *(uint32_t*)&r;
}
// streaming 32-bit store (for p fp16x2)
__device__ __forceinline__ void stcs32(__half* p, __half2 v) {
    asm volatile("st.global.cs.b32 [%0], %1;\n" :: "l"(p), "r"(*(uint32_t*)&v));
}
// streaming float2 store (final fp32 output)
__device__ __forceinline__ void stcs64f(float* p, float2 v) {
    asm volatile("st.global.cs.v2.f32 [%0], {%1, %2};\n"
                 :: "l"(p), "f"(v.x), "f"(v.y));
}
// streaming read-once float4 load
__device__ __forceinline__ float4 ldcs128(const float4* p) {
    float4 v;
    asm volatile("ld.global.cs.nc.v4.f32 {%0, %1, %2, %3}, [%4];"
                 : "=f"(v.x), "=f"(v.y), "=f"(v.z), "=f"(v.w) : "l"(p));
    return v;
}

// smem stride (halves): rows are 144 B (odd multiple of 16B -> conflict-free)
#define STRH64 72

// ---------------------------------------------------------------------------
// Merged fp32 -> fp16 conversion for all 7 buffers (compile-time boundaries)
// ---------------------------------------------------------------------------
#define C_N1 1048576u            // query float4s
#define C_N2 2097152u            // + key
#define C_N3 3145728u            // + value
#define C_N4 3407872u            // + Wq
#define C_N5 3538944u            // + Wk
#define C_N6 3670016u            // + Wv
#define C_NT 3932160u            // + Wo

__global__ void conv_all(const float4* __restrict__ q, const float4* __restrict__ k,
                         const float4* __restrict__ v, const float4* __restrict__ wq,
                         const float4* __restrict__ wk, const float4* __restrict__ wv,
                         const float4* __restrict__ wo,
                         __half2* dq, __half2* dk, __half2* dv, __half2* dwq,
                         __half2* dwk, __half2* dwv, __half2* dwo) {
    unsigned i = blockIdx.x * 256 + threadIdx.x;
    if (i >= C_NT) return;
    const float4* s; __half2* d; unsigned off;
    if (i < C_N3) {
        if (i < C_N1)      { s = q; d = dq; off = i; }
        else if (i < C_N2) { s = k; d = dk; off = i - C_N1; }
        else               { s = v; d = dv; off = i - C_N2; }
    } else {
        if (i < C_N4)      { s = wq; d = dwq; off = i - C_N3; }
        else if (i < C_N5) { s = wk; d = dwk; off = i - C_N4; }
        else if (i < C_N6) { s = wv; d = dwv; off = i - C_N5; }
        else               { s = wo; d = dwo; off = i - C_N6; }
    }
    float4 vv = ldcs128(s + off);   // read-once: don't pollute L2
    d[2 * off]     = __floats2half2_rn(vv.x, vv.y);
    d[2 * off + 1] = __floats2half2_rn(vv.z, vv.w);
}

// ===========================================================================
// GEMM core (BK=64, block 128x128, 8 warps 4x2, warp tile 32x64). 2-stage.
// ===========================================================================
template <bool HALF_OUT>
__device__ __forceinline__
void gemm_body(const __half* __restrict__ A, const __half* __restrict__ W,
               const float* __restrict__ bias, void* __restrict__ Cv,
               int N, int K, int bm, int bn, __half* smh) {
    __half* As = smh;                      // [2][128][STRH64]
    __half* Bs = smh + 2 * 128 * STRH64;   // [2][128][STRH64]

    const int tid = threadIdx.x;
    const int w = tid >> 5, lane = tid & 31;
    const int g = lane >> 2, tig = lane & 3;
    const int wm = (w & 3) * 32, wn = (w >> 2) * 64;

    float acc[2][8][4] = {};
    const int S = K >> 6;

    auto prefetch = [&](int s, int buf) {
        const int k0 = s * 64;
        __half* Ab = As + buf * 128 * STRH64;
        __half* Bb = Bs + buf * 128 * STRH64;
        #pragma unroll
        for (int i = 0; i < 4; i++) {
            int ch = tid + i * 256;       // 0..1023
            int row = ch >> 3;            // 0..127
            int kc = (ch & 7) * 8;        // 0..56 halves
            cp16(Ab + row * STRH64 + kc, A + (size_t)(bm + row) * K + k0 + kc);
            cp16(Bb + row * STRH64 + kc, W + (size_t)(bn + row) * K + k0 + kc);
        }
    };

    prefetch(0, 0);
    cp_commit();

    for (int s = 0; s < S; s++) {
        const int buf = s & 1;
        if (s + 1 < S) { prefetch(s + 1, buf ^ 1); cp_commit(); cp_wait<1>(); }
        else           { cp_wait<0>(); }
        __syncthreads();

        const __half* Ab = As + buf * 128 * STRH64;
        const __half* Bb = Bs + buf * 128 * STRH64;
        #pragma unroll
        for (int kk = 0; kk < 64; kk += 16) {
            uint32_t af[2][4], bf[8][2];
            #pragma unroll
            for (int mf = 0; mf < 2; mf++) {
                int mb = wm + mf * 16;
                af[mf][0] = lds32h(Ab + (mb + g) * STRH64 + kk + 2 * tig);
                af[mf][1] = lds32h(Ab + (mb + g + 8) * STRH64 + kk + 2 * tig);
                af[mf][2] = lds32h(Ab + (mb + g) * STRH64 + kk + 2 * tig + 8);
                af[mf][3] = lds32h(Ab + (mb + g + 8) * STRH64 + kk + 2 * tig + 8);
            }
            #pragma unroll
            for (int nf = 0; nf < 8; nf++) {
                int nb = wn + nf * 8 + g;
                bf[nf][0] = lds32h(Bb + nb * STRH64 + kk + 2 * tig);
                bf[nf][1] = lds32h(Bb + nb * STRH64 + kk + 2 * tig + 8);
            }
            #pragma unroll
            for (int mf = 0; mf < 2; mf++)
                #pragma unroll
                for (int nf = 0; nf < 8; nf++)
                    mma_f16(acc[mf][nf], af[mf], bf[nf]);
        }
        __syncthreads();
    }

    #pragma unroll
    for (int mf = 0; mf < 2; mf++) {
        #pragma unroll
        for (int nf = 0; nf < 8; nf++) {
            int row = bm + wm + mf * 16 + g;
            int col = bn + wn + nf * 8 + tig * 2;
            float b0 = __ldg(bias + col);
            float b1 = __ldg(bias + col + 1);
            float c0 = acc[mf][nf][0] + b0, c1 = acc[mf][nf][1] + b1;
            float c2 = acc[mf][nf][2] + b0, c3 = acc[mf][nf][3] + b1;
            if (HALF_OUT) {
                __half* C = (__half*)Cv;
                *(__half2*)(C + (size_t)row * N + col) = __floats2half2_rn(c0, c1);
                *(__half2*)(C + (size_t)(row + 8) * N + col) = __floats2half2_rn(c2, c3);
            } else {
                // final fp32 output: streaming stores (never re-read on device)
                float* C = (float*)Cv;
                stcs64f(C + (size_t)row * N + col, make_float2(c0, c1));
                stcs64f(C + (size_t)(row + 8) * N + col, make_float2(c2, c3));
            }
        }
    }
}

// ===========================================================================
// Merged Q/K/V projection: one launch, 1280 blocks.
// ===========================================================================
__global__ __launch_bounds__(256, 2)
void gemm_qkv(const __half* __restrict__ inq, const __half* __restrict__ ink,
              const __half* __restrict__ inv, const __half* __restrict__ wh,
              const float* __restrict__ bq, const float* __restrict__ bk,
              const float* __restrict__ bv,
              __half* __restrict__ qh, __half* __restrict__ kh,
              __half* __restrict__ vh) {
    extern __shared__ __half smh[];
    int blk = blockIdx.x;
    const __half *A, *W;
    const float* bias;
    __half* C;
    int K;
    if (blk < 256) {
        A = inq; W = wh + WQ_OFF; bias = bq; C = qh; K = QD;
    } else if (blk < 768) {
        blk -= 256;
        A = ink; W = wh + WK_OFF; bias = bk; C = kh; K = KD;
    } else {
        blk -= 768;
        A = inv; W = wh + WV_OFF; bias = bv; C = vh; K = KD;
    }
    const int bn = (blk & 7) * 128;
    const int bm = (blk >> 3) * 128;
    gemm_body<true>(A, W, bias, C, QD, K, bm, bn, smh);
}

// ===========================================================================
// O projection (fp32 out, streaming): grid (QD/128, BB*LQ/128)
// ===========================================================================
__global__ __launch_bounds__(256, 2)
void gemm_o(const __half* __restrict__ ctxh, const __half* __restrict__ wo,
            const float* __restrict__ bo, float* __restrict__ out) {
    extern __shared__ __half smh[];
    gemm_body<false>(ctxh, wo, bo, out, QD, QD,
                     blockIdx.y * 128, blockIdx.x * 128, smh);
}

// ===========================================================================
// Scores: p_tile = exp(SCALE*q.k - m_sub) fp16 (streaming stores) +
// per-(row, 64-col) stats. Grid: (LK/128, LQ/128, BB*NH)
// ===========================================================================
__global__ __launch_bounds__(256, 2)
void scores_h(const __half* __restrict__ qm, const __half* __restrict__ km,
              __half* __restrict__ ph, float* __restrict__ pm,
              float* __restrict__ ps) {
    extern __shared__ __half smh[];
    __half* As = smh;                      // [128][STRH64]
    __half* Bs = smh + 128 * STRH64;       // [128][STRH64]

    const int bh = blockIdx.z;
    const int b = bh >> 4, h = bh & 15;
    const __half* Aq = qm + (size_t)b * LQ * QD + h * HD;
    const __half* Ak = km + (size_t)b * LK * QD + h * HD;
    __half* Pp = ph + (size_t)bh * LQ * LK;

    const int tid = threadIdx.x;
    const int bm = blockIdx.y * 128;
    const int bn = blockIdx.x * 128;
    const int w = tid >> 5, lane = tid & 31;
    const int g = lane >> 2, tig = lane & 3;
    const int wm = (w & 3) * 32, wn = (w >> 2) * 64;
    const int sub = blockIdx.x * 2 + (w >> 2);

    #pragma unroll
    for (int i = 0; i < 4; i++) {
        int ch = tid + i * 256;
        int row = ch >> 3;
        int kc = (ch & 7) * 8;
        cp16(As + row * STRH64 + kc, Aq + (size_t)(bm + row) * QD + kc);
        cp16(Bs + row * STRH64 + kc, Ak + (size_t)(bn + row) * QD + kc);
    }
    cp_commit();
    cp_wait<0>();
    __syncthreads();

    float acc[2][8][4] = {};
    #pragma unroll
    for (int kk = 0; kk < 64; kk += 16) {
        uint32_t af[2][4], bf[8][2];
        #pragma unroll
        for (int mf = 0; mf < 2; mf++) {
            int mb = wm + mf * 16;
            af[mf][0] = lds32h(As + (mb + g) * STRH64 + kk + 2 * tig);
            af[mf][1] = lds32h(As + (mb + g + 8) * STRH64 + kk + 2 * tig);
            af[mf][2] = lds32h(As + (mb + g) * STRH64 + kk + 2 * tig + 8);
            af[mf][3] = lds32h(As + (mb + g + 8) * STRH64 + kk + 2 * tig + 8);
        }
        #pragma unroll
        for (int nf = 0; nf < 8; nf++) {
            int nb = wn + nf * 8 + g;
            bf[nf][0] = lds32h(Bs + nb * STRH64 + kk + 2 * tig);
            bf[nf][1] = lds32h(Bs + nb * STRH64 + kk + 2 * tig + 8);
        }
        #pragma unroll
        for (int mf = 0; mf < 2; mf++)
            #pragma unroll
            for (int nf = 0; nf < 8; nf++)
                mma_f16(acc[mf][nf], af[mf], bf[nf]);
    }

    #pragma unroll
    for (int mf = 0; mf < 2; mf++) {
        float mA = -1e30f, mB = -1e30f;
        #pragma unroll
        for (int nf = 0; nf < 8; nf++) {
            #pragma unroll
            for (int q = 0; q < 4; q++) acc[mf][nf][q] *= SCALE;
            mA = fmaxf(mA, fmaxf(acc[mf][nf][0], acc[mf][nf][1]));
            mB = fmaxf(mB, fmaxf(acc[mf][nf][2], acc[mf][nf][3]));
        }
        mA = fmaxf(mA, __shfl_xor_sync(0xFFFFFFFFu, mA, 1));
        mA = fmaxf(mA, __shfl_xor_sync(0xFFFFFFFFu, mA, 2));
        mB = fmaxf(mB, __shfl_xor_sync(0xFFFFFFFFu, mB, 1));
        mB = fmaxf(mB, __shfl_xor_sync(0xFFFFFFFFu, mB, 2));

        float sA = 0.f, sB = 0.f;
        #pragma unroll
        for (int nf = 0; nf < 8; nf++) {
            acc[mf][nf][0] = __expf(acc[mf][nf][0] - mA);
            acc[mf][nf][1] = __expf(acc[mf][nf][1] - mA);
            acc[mf][nf][2] = __expf(acc[mf][nf][2] - mB);
            acc[mf][nf][3] = __expf(acc[mf][nf][3] - mB);
            sA += acc[mf][nf][0] + acc[mf][nf][1];
            sB += acc[mf][nf][2] + acc[mf][nf][3];
        }
        sA += __shfl_xor_sync(0xFFFFFFFFu, sA, 1);
        sA += __shfl_xor_sync(0xFFFFFFFFu, sA, 2);
        sB += __shfl_xor_sync(0xFFFFFFFFu, sB, 1);
        sB += __shfl_xor_sync(0xFFFFFFFFu, sB, 2);

        int rowA = bm + wm + mf * 16 + g;
        #pragma unroll
        for (int nf = 0; nf < 8; nf++) {
            int col = bn + wn + nf * 8 + tig * 2;
            stcs32(Pp + (size_t)rowA * LK + col,
                   __floats2half2_rn(acc[mf][nf][0], acc[mf][nf][1]));
            stcs32(Pp + (size_t)(rowA + 8) * LK + col,
                   __floats2half2_rn(acc[mf][nf][2], acc[mf][nf][3]));
        }
        if (tig == 0) {
            size_t rA = (size_t)bh * LQ + rowA;
            pm[rA * NSUB + sub] = mA; ps[rA * NSUB + sub] = sA;
            pm[(rA + 8) * NSUB + sub] = mB; ps[(rA + 8) * NSUB + sub] = sB;
        }
    }
}

// ===========================================================================
// Per-row factors: ONE WARP PER TWO ROWS (ILP-2 butterfly chains).
// Warp w of block handles rows base+2w, base+2w+1; lane t owns subtile t.
// Grid: TOTROWS/16 blocks x 256 threads (8 warps x 2 rows).
// ===========================================================================
__global__ __launch_bounds__(256)
void reduce_stats_k(const float* __restrict__ pm,
                    const float* __restrict__ ps,
                    float* __restrict__ fac) {
    const int w = threadIdx.x >> 5;
    const int lane = threadIdx.x & 31;
    const int row0 = blockIdx.x * 16 + w * 2;
    const size_t i0 = (size_t)row0 * NSUB + lane;
    const size_t i1 = i0 + NSUB;

    float m0 = pm[i0], m1 = pm[i1];
    float s0 = ps[i0], s1 = ps[i1];

    float r0 = m0, r1 = m1;
    #pragma unroll
    for (int o = 16; o > 0; o >>= 1) {
        r0 = fmaxf(r0, __shfl_xor_sync(0xFFFFFFFFu, r0, o));
        r1 = fmaxf(r1, __shfl_xor_sync(0xFFFFFFFFu, r1, o));
    }

    float e0 = __expf(m0 - r0);
    float e1 = __expf(m1 - r1);
    float l0 = s0 * e0;
    float l1 = s1 * e1;
    #pragma unroll
    for (int o = 16; o > 0; o >>= 1) {
        l0 += __shfl_xor_sync(0xFFFFFFFFu, l0, o);
        l1 += __shfl_xor_sync(0xFFFFFFFFu, l1, o);
    }

    fac[i0] = e0 / l0;
    fac[i1] = e1 / l1;
}

// ===========================================================================
// Context (BK=64, 2-stage): attn fp32 = p*fac (streaming store);
// ctx = (p*fac) @ V. Grid: (LQ/128, BB*NH). Slab s == stat subtile s.
// ===========================================================================
__global__ __launch_bounds__(256, 2)
void ctx_h(const __half* __restrict__ ph, const __half* __restrict__ vh,
           float* __restrict__ attn, __half* __restrict__ ctx,
           const float* __restrict__ fac) {
    extern __shared__ char smraw2[];
    __half* Ps = (__half*)smraw2;                              // [2][128][STRH64]
    __half* Vs = (__half*)(smraw2 + 2 * 128 * STRH64 * 2);     // [2][64][STRH64]
    float* facs = (float*)(smraw2 + 2 * 128 * STRH64 * 2 + 2 * 64 * STRH64 * 2);

    const int bh = blockIdx.y;
    const int b = bh >> 4, h = bh & 15;
    const __half* Pp = ph + (size_t)bh * LQ * LK;
    const __half* Vp = vh + (size_t)b * LK * QD + h * HD;
    float* Ap = attn + (size_t)bh * LQ * LK;

    const int tid = threadIdx.x;
    const int bm = blockIdx.x * 128;
    const int w = tid >> 5, lane = tid & 31;
    const int g = lane >> 2, tig = lane & 3;
    const int wm = (w & 3) * 32, wn = (w >> 2) * 32;

    {
        const float* fsrc = fac + ((size_t)bh * LQ + bm) * NSUB;
        #pragma unroll
        for (int i = 0; i < (128 * NSUB) / 256; i++)
            facs[i * 256 + tid] = fsrc[i * 256 + tid];
    }

    float acc[2][4][4] = {};

    auto prefetch = [&](int s, int buf) {
        const int k0 = s * 64;
        __half* Pb = Ps + buf * 128 * STRH64;
        __half* Vb = Vs + buf * 64 * STRH64;
        #pragma unroll
        for (int i = 0; i < 4; i++) {
            int ch = tid + i * 256;       // 0..1023
            int row = ch >> 3;            // 0..127
            int kc = (ch & 7) * 8;        // 0..56
            cp16(Pb + row * STRH64 + kc, Pp + (size_t)(bm + row) * LK + k0 + kc);
        }
        #pragma unroll
        for (int i = 0; i < 2; i++) {
            int ch = tid + i * 256;       // 0..511
            int kr = ch >> 3;             // 0..63
            int nc = (ch & 7) * 8;        // 0..56
            cp16(Vb + kr * STRH64 + nc, Vp + (size_t)(k0 + kr) * QD + nc);
        }
    };

    prefetch(0, 0);
    cp_commit();

    const int S = LK / 64;   // 32 slabs; slab s == subtile s
    for (int s = 0; s < S; s++) {
        const int buf = s & 1;
        if (s + 1 < S) { prefetch(s + 1, buf ^ 1); cp_commit(); cp_wait<1>(); }
        else           { cp_wait<0>(); }
        __syncthreads();

        const __half* Pb = Ps + buf * 128 * STRH64;
        const __half* Vb = Vs + buf * 64 * STRH64;
        const int k0 = s * 64;

        // attn write: p_fp32 = half(p) * factor (streaming store, no reuse)
        #pragma unroll
        for (int i = 0; i < 8; i++) {
            int ch = tid + i * 256;       // 0..2047
            int row = ch >> 4;            // 0..127
            int kc = (ch & 15) * 4;       // 0..60
            float f = facs[row * NSUB + s];
            __half2 h0 = *(const __half2*)(Pb + row * STRH64 + kc);
            __half2 h1 = *(const __half2*)(Pb + row * STRH64 + kc + 2);
            float4 o;
            o.x = __low2float(h0) * f;  o.y = __high2float(h0) * f;
            o.z = __low2float(h1) * f;  o.w = __high2float(h1) * f;
            __stcs((float4*)(Ap + (size_t)(bm + row) * LK + k0 + kc), o);
        }

        #pragma unroll
        for (int kk = 0; kk < 64; kk += 16) {
            uint32_t af[2][4], bf[4][2];
            #pragma unroll
            for (int mf = 0; mf < 2; mf++) {
                int mb = wm + mf * 16;
                __half2 fg = __float2half2_rn(facs[(mb + g) * NSUB + s]);
                __half2 f8 = __float2half2_rn(facs[(mb + g + 8) * NSUB + s]);
                af[mf][0] = h2scale(lds32h(Pb + (mb + g) * STRH64 + kk + 2 * tig), fg);
                af[mf][1] = h2scale(lds32h(Pb + (mb + g + 8) * STRH64 + kk + 2 * tig), f8);
                af[mf][2] = h2scale(lds32h(Pb + (mb + g) * STRH64 + kk + 2 * tig + 8), fg);
                af[mf][3] = h2scale(lds32h(Pb + (mb + g + 8) * STRH64 + kk + 2 * tig + 8), f8);
            }
            #pragma unroll
            for (int nf = 0; nf < 4; nf++) {
                int nb = wn + nf * 8 + g;
                __half2 b0 = __halves2half2(Vb[(kk + 2 * tig) * STRH64 + nb],
                                            Vb[(kk + 2 * tig + 1) * STRH64 + nb]);
                __half2 b1 = __halves2half2(Vb[(kk + 2 * tig + 8) * STRH64 + nb],
                                            Vb[(kk + 2 * tig + 9) * STRH64 + nb]);
                bf[nf][0] = *(uint32_t*)&b0;
                bf[nf][1] = *(uint32_t*)&b1;
            }
            #pragma unroll
            for (int mf = 0; mf < 2; mf++)
                #pragma unroll
                for (int nf = 0; nf < 4; nf++)
                    mma_f16(acc[mf][nf], af[mf], bf[nf]);
        }
        __syncthreads();
    }

    #pragma unroll
    for (int mf = 0; mf < 2; mf++) {
        #pragma unroll
        for (int nf = 0; nf < 4; nf++) {
            int row = bm + wm + mf * 16 + g;
            int col = h * HD + wn + nf * 8 + tig * 2;
            *(__half2*)(ctx + (size_t)(b * LQ + row) * QD + col) =
                __floats2half2_rn(acc[mf][nf][0], acc[mf][nf][1]);
            *(__half2*)(ctx + (size_t)(b * LQ + row + 8) * QD + col) =
                __floats2half2_rn(acc[mf][nf][2], acc[mf][nf][3]);
        }
    }
}

// ---------------------------------------------------------------------------
// kernel_launch
// ---------------------------------------------------------------------------
extern "C" void kernel_launch(void* const* d_in, const int* in_sizes, int n_in,
                              void* d_out, int out_size) {
    const float* query = (const float*)d_in[0];
    const float* key   = (const float*)d_in[1];
    const float* value = (const float*)d_in[2];
    const float* Wq = (const float*)d_in[3];
    const float* bq = (const float*)d_in[4];
    const float* Wk = (const float*)d_in[5];
    const float* bk = (const float*)d_in[6];
    const float* Wv = (const float*)d_in[7];
    const float* bv = (const float*)d_in[8];
    const float* Wo = (const float*)d_in[9];
    const float* bo = (const float*)d_in[10];

    float* out  = (float*)d_out;
    float* attn = out + (size_t)BB * LQ * QD;

    __half *inq, *ink, *inv, *wh, *qh, *kh, *vhp, *ctxh, *php;
    float *pm, *ps, *facp;
    cudaGetSymbolAddress((void**)&inq, g_inq);
    cudaGetSymbolAddress((void**)&ink, g_ink);
    cudaGetSymbolAddress((void**)&inv, g_inv);
    cudaGetSymbolAddress((void**)&wh,  g_wh);
    cudaGetSymbolAddress((void**)&qh,  g_qh);
    cudaGetSymbolAddress((void**)&kh,  g_kh);
    cudaGetSymbolAddress((void**)&vhp, g_vh);
    cudaGetSymbolAddress((void**)&ctxh, g_ctxh);
    cudaGetSymbolAddress((void**)&php, g_ph);
    cudaGetSymbolAddress((void**)&pm, g_pm);
    cudaGetSymbolAddress((void**)&ps, g_ps);
    cudaGetSymbolAddress((void**)&facp, g_fac);

    const int SMEM_GEMM = 2 * 2 * 128 * STRH64 * 2;                      // 73728 B
    const int SMEM_SC   = 2 * 128 * STRH64 * 2;                          // 36864 B
    const int SMEM_CTX  = 2 * 128 * STRH64 * 2 + 2 * 64 * STRH64 * 2
                        + 128 * NSUB * 4;                                // 71680 B
    cudaFuncSetAttribute(gemm_qkv, cudaFuncAttributeMaxDynamicSharedMemorySize, SMEM_GEMM);
    cudaFuncSetAttribute(gemm_o,   cudaFuncAttributeMaxDynamicSharedMemorySize, SMEM_GEMM);
    cudaFuncSetAttribute(scores_h, cudaFuncAttributeMaxDynamicSharedMemorySize, SMEM_SC);
    cudaFuncSetAttribute(ctx_h,    cudaFuncAttributeMaxDynamicSharedMemorySize, SMEM_CTX);

    // fp32 -> fp16 conversions (single merged launch, streaming reads)
    conv_all<<<C_NT / 256, 256>>>(
        (const float4*)query, (const float4*)key, (const float4*)value,
        (const float4*)Wq, (const float4*)Wk, (const float4*)Wv, (const float4*)Wo,
        (__half2*)inq, (__half2*)ink, (__half2*)inv,
        (__half2*)(wh + WQ_OFF), (__half2*)(wh + WK_OFF),
        (__half2*)(wh + WV_OFF), (__half2*)(wh + WO_OFF));

    // Q/K/V projections in ONE launch (1280 blocks)
    gemm_qkv<<<1280, 256, SMEM_GEMM>>>(inq, ink, inv, wh, bq, bk, bv, qh, kh, vhp);

    // Attention
    scores_h<<<dim3(LK / 128, LQ / 128, BB * NH), 256, SMEM_SC>>>(qh, kh, php, pm, ps);
    reduce_stats_k<<<TOTROWS / 16, 256>>>(pm, ps, facp);
    ctx_h<<<dim3(LQ / 128, BB * NH), 256, SMEM_CTX>>>(php, vhp, attn, ctxh, facp);

    // Output projection (fp32 out, streaming stores)
    gemm_o<<<dim3(QD / 128, (BB * LQ) / 128), 256, SMEM_GEMM>>>(ctxh, wh + WO_OFF, bo, out);
}